// round 13
// baseline (speedup 1.0000x reference)
#include <cuda_runtime.h>
#include <cuda_bf16.h>
#include <math.h>
#include <stdint.h>

#define N_ELEM 4194304   // elements per tensor (2*16*2048*64)
#define SLICE  131072    // one batch-head slice
#define NBH    32
#define R_IDX  4152360u  // 0-based order-statistic index of the 0.99 quantile
#define OUT_HAT1  134217728u
#define OUT_HAT2  138412032u

// ---------------- device scratch ----------------
__device__ float    g_xm1[SLICE];
__device__ float    g_xm2T[SLICE];
__device__ unsigned g_hist1a[2 * 65536];
__device__ unsigned g_hist2a[2 * 65536];
__device__ unsigned g_below[2];
__device__ unsigned g_bucket[2];
__device__ unsigned g_rankin[2];
__device__ float    g_t[2];
__device__ unsigned g_maxbits[2];
__device__ float    g_Bpart[32 * 4096];
__device__ float    g_P[2 * 4096];
__device__ float    g_LR1[SLICE];
__device__ float    g_LR2T[SLICE];

// ---------------- helpers ----------------
__device__ __forceinline__ uint32_t s2u(const void* p) {
    uint32_t a;
    asm("{ .reg .u64 t; cvta.to.shared.u64 t, %1; cvt.u32.u64 %0, t; }" : "=r"(a) : "l"(p));
    return a;
}
#define SWZ(o) ((o) ^ (((o) >> 3) & 0x70))

__device__ __forceinline__ void ldmat4(uint32_t& r0, uint32_t& r1, uint32_t& r2, uint32_t& r3,
                                       uint32_t addr) {
    asm volatile("ldmatrix.sync.aligned.m8n8.x4.shared.b16 {%0,%1,%2,%3}, [%4];"
                 : "=r"(r0), "=r"(r1), "=r"(r2), "=r"(r3) : "r"(addr));
}
__device__ __forceinline__ void ldmat4t(uint32_t& r0, uint32_t& r1, uint32_t& r2, uint32_t& r3,
                                        uint32_t addr) {
    asm volatile("ldmatrix.sync.aligned.m8n8.x4.trans.shared.b16 {%0,%1,%2,%3}, [%4];"
                 : "=r"(r0), "=r"(r1), "=r"(r2), "=r"(r3) : "r"(addr));
}
__device__ __forceinline__ void mma16816(float* d, const uint32_t* a, uint32_t b0, uint32_t b1) {
    asm volatile(
        "mma.sync.aligned.m16n8k16.row.col.f32.bf16.bf16.f32 "
        "{%0,%1,%2,%3}, {%4,%5,%6,%7}, {%8,%9}, {%0,%1,%2,%3};"
        : "+f"(d[0]), "+f"(d[1]), "+f"(d[2]), "+f"(d[3])
        : "r"(a[0]), "r"(a[1]), "r"(a[2]), "r"(a[3]), "r"(b0), "r"(b1));
}

// ---------------- zero scratch ----------------
__global__ void k_zero() {
    int i = blockIdx.x * blockDim.x + threadIdx.x;
    if (i < 2 * 65536) { g_hist1a[i] = 0u; g_hist2a[i] = 0u; }
    if (i < 2) { g_below[i] = 0u; g_maxbits[i] = 0u; }
}

// ---------------- means + level-1 histogram ----------
__global__ void k_mean_hist(const float* __restrict__ x1, const float* __restrict__ x2) {
    int i = blockIdx.x * blockDim.x + threadIdx.x;
    float s1 = 0.f, s2 = 0.f;
    unsigned c1 = 0, c2 = 0;
    #pragma unroll 4
    for (int bh = 0; bh < NBH; bh++) {
        float v1 = x1[bh * SLICE + i];
        s1 += v1;
        unsigned b1 = __float_as_uint(v1) & 0x7FFFFFFFu;
        if (b1 >= 0x40000000u) atomicAdd(&g_hist1a[b1 >> 16], 1u); else c1++;
        float v2 = x2[bh * SLICE + i];
        s2 += v2;
        unsigned b2 = __float_as_uint(v2) & 0x7FFFFFFFu;
        if (b2 >= 0x40000000u) atomicAdd(&g_hist1a[65536 + (b2 >> 16)], 1u); else c2++;
    }
    g_xm1[i]  = s1 * 0.03125f;
    g_xm2T[i] = s2 * 0.03125f;
    #pragma unroll
    for (int off = 16; off > 0; off >>= 1) {
        c1 += __shfl_down_sync(0xFFFFFFFFu, c1, off);
        c2 += __shfl_down_sync(0xFFFFFFFFu, c2, off);
    }
    if ((threadIdx.x & 31) == 0) {
        atomicAdd(&g_below[0], c1);
        atomicAdd(&g_below[1], c2);
    }
}

// ---------------- B partials — unified [s][d] staging, float4 inner loads ----
__global__ __launch_bounds__(256, 1)
void k_B() {
    __shared__ float sm[128 * 72];
    int bid = blockIdx.x;
    int tn = bid >> 4, chunk = bid & 15;
    int t = threadIdx.x;
    int s0 = chunk * 128;

    if (tn == 0) {
        for (int idx = t; idx < 2048; idx += 256) {
            int row = idx >> 4, f4 = (idx & 15) * 4;
            float4 v = *(const float4*)&g_xm1[(s0 + row) * 64 + f4];
            *(float4*)&sm[row * 72 + f4] = v;
        }
    } else {
        for (int idx = t; idx < 2048; idx += 256) {
            int d = idx >> 5, sblk = (idx & 31) * 4;
            float4 v = *(const float4*)&g_xm2T[d * 2048 + s0 + sblk];
            sm[(sblk + 0) * 72 + d] = v.x;
            sm[(sblk + 1) * 72 + d] = v.y;
            sm[(sblk + 2) * 72 + d] = v.z;
            sm[(sblk + 3) * 72 + d] = v.w;
        }
    }
    __syncthreads();

    int d1 = t >> 2, d2b = (t & 3) * 16;
    float acc[16];
    #pragma unroll
    for (int j = 0; j < 16; j++) acc[j] = 0.f;
    for (int s = 0; s < 128; s++) {
        float a = sm[s * 72 + d1];
        const float4* bp = (const float4*)&sm[s * 72 + d2b];
        float4 b0 = bp[0], b1 = bp[1], b2 = bp[2], b3 = bp[3];
        acc[0]  = fmaf(a, b0.x, acc[0]);  acc[1]  = fmaf(a, b0.y, acc[1]);
        acc[2]  = fmaf(a, b0.z, acc[2]);  acc[3]  = fmaf(a, b0.w, acc[3]);
        acc[4]  = fmaf(a, b1.x, acc[4]);  acc[5]  = fmaf(a, b1.y, acc[5]);
        acc[6]  = fmaf(a, b1.z, acc[6]);  acc[7]  = fmaf(a, b1.w, acc[7]);
        acc[8]  = fmaf(a, b2.x, acc[8]);  acc[9]  = fmaf(a, b2.y, acc[9]);
        acc[10] = fmaf(a, b2.z, acc[10]); acc[11] = fmaf(a, b2.w, acc[11]);
        acc[12] = fmaf(a, b3.x, acc[12]); acc[13] = fmaf(a, b3.y, acc[13]);
        acc[14] = fmaf(a, b3.z, acc[14]); acc[15] = fmaf(a, b3.w, acc[15]);
    }
    float* dst = &g_Bpart[bid * 4096 + d1 * 64 + d2b];
    #pragma unroll
    for (int j = 0; j < 16; j++) dst[j] = acc[j];
}

// ---------------- Jacobi — fused one-pass 2x2-block rotation, 2 barriers/round
// Thread t = (a<<5)|b owns the 2x2 block (row-pair a, col-pair b) of A and
// V rows {2a,2a+1} of col-pair b. Blocks are disjoint -> no intra-round hazard.
#define JAC_BLOCK_SMEM (150 * 1024)

__global__ __launch_bounds__(1024, 1)
void k_jacobi() {
    extern __shared__ char jac_pad[];   // occupancy blocker, untouched
    __shared__ float A[64 * 65];
    __shared__ float V[64 * 65];
    __shared__ int    pq[32];
    __shared__ float2 cs[32];
    __shared__ int   isTop[64], topIdx[16];
    int tn = blockIdx.x;
    int t = threadIdx.x;
    int a = t >> 5, b = t & 31;
    (void)jac_pad;

    #pragma unroll
    for (int k2 = 0; k2 < 4; k2++) {
        int idx = t + k2 * 1024;
        int r = idx >> 6, c = idx & 63;
        float v = 0.f;
        #pragma unroll 4
        for (int p = 0; p < 16; p++) v += g_Bpart[(tn * 16 + p) * 4096 + idx];
        A[r * 65 + c] = v;
        V[r * 65 + c] = (r == c) ? 1.f : 0.f;
    }
    __syncthreads();

    for (int rnd = 0; rnd < 6 * 63; rnd++) {
        int r = rnd % 63;
        // head: 32 threads compute pairs + rotation coefficients
        if (t < 32) {
            int p, q;
            if (t == 0) { p = 0; q = 1 + r; }
            else {
                int a1 = r + t;      if (a1 >= 63) a1 -= 63;
                int a2 = r + 63 - t; if (a2 >= 63) a2 -= 63;
                p = 1 + a1; q = 1 + a2;
            }
            if (p > q) { int tmp = p; p = q; q = tmp; }
            float app = A[p * 65 + p], aqq = A[q * 65 + q], apq = A[p * 65 + q];
            float c = 1.f, s = 0.f;
            if (fabsf(apq) > 1e-20f) {
                float th = __fdividef(aqq - app, 2.0f * apq);
                float rr = __fsqrt_rn(fmaf(th, th, 1.f));
                float tt = __fdividef((th >= 0.f) ? 1.f : -1.f, fabsf(th) + rr);
                float ci = __frsqrt_rn(fmaf(tt, tt, 1.f));
                c = ci; s = tt * ci;
            }
            pq[t] = p | (q << 8);
            cs[t] = make_float2(c, s);
        }
        __syncthreads();
        // fused two-sided update of the (a,b) 2x2 block of A
        int pka = pq[a];
        int pa = pka & 0xFF, qa = pka >> 8;
        float2 csa = cs[a];
        int pkb = pq[b];
        int pb = pkb & 0xFF, qb = pkb >> 8;
        float2 csb = cs[b];
        {
            float t00 = A[pa * 65 + pb], t01 = A[pa * 65 + qb];
            float t10 = A[qa * 65 + pb], t11 = A[qa * 65 + qb];
            // right (column) rotation with (cb,sb)
            float u00 = csb.x * t00 - csb.y * t01;
            float u01 = csb.y * t00 + csb.x * t01;
            float u10 = csb.x * t10 - csb.y * t11;
            float u11 = csb.y * t10 + csb.x * t11;
            // left (row) rotation with (ca,sa)
            A[pa * 65 + pb] = csa.x * u00 - csa.y * u10;
            A[qa * 65 + pb] = csa.y * u00 + csa.x * u10;
            A[pa * 65 + qb] = csa.x * u01 - csa.y * u11;
            A[qa * 65 + qb] = csa.y * u01 + csa.x * u11;
        }
        // V column rotation: rows 2a, 2a+1 of col-pair b
        {
            int r0 = (a << 1), r1 = r0 + 1;
            float v00 = V[r0 * 65 + pb], v01 = V[r0 * 65 + qb];
            float v10 = V[r1 * 65 + pb], v11 = V[r1 * 65 + qb];
            V[r0 * 65 + pb] = csb.x * v00 - csb.y * v01;
            V[r0 * 65 + qb] = csb.y * v00 + csb.x * v01;
            V[r1 * 65 + pb] = csb.x * v10 - csb.y * v11;
            V[r1 * 65 + qb] = csb.y * v10 + csb.x * v11;
        }
        __syncthreads();
    }

    if (t < 64) {
        float lam = A[t * 65 + t];
        int rank = 0;
        for (int j = 0; j < 64; j++) {
            float lj = A[j * 65 + j];
            if (lj > lam || (lj == lam && j < t)) rank++;
        }
        isTop[t] = (rank < 16) ? 1 : 0;
    }
    __syncthreads();
    if (t == 0) {
        int n = 0;
        for (int i = 0; i < 64; i++) if (isTop[i]) topIdx[n++] = i;
    }
    __syncthreads();
    #pragma unroll
    for (int k2 = 0; k2 < 4; k2++) {
        int idx = t + k2 * 1024;
        int r = idx >> 6, c = idx & 63;
        float sum = 0.f;
        #pragma unroll
        for (int k = 0; k < 16; k++) {
            int i = topIdx[k];
            sum = fmaf(V[r * 65 + i], V[c * 65 + i], sum);
        }
        g_P[tn * 4096 + idx] = sum;
    }
}

// ---------------- histogram select ----------------
__global__ void k_sel(int mode) {
    int tn = blockIdx.x;
    const unsigned* h = (mode == 0) ? &g_hist1a[tn * 65536] : &g_hist2a[tn * 65536];
    __shared__ unsigned ss[1024];
    unsigned t = threadIdx.x;
    unsigned s = 0;
    #pragma unroll 8
    for (int j = 0; j < 64; j++) s += h[t * 64 + j];
    ss[t] = s;
    __syncthreads();
    for (int off = 1; off < 1024; off <<= 1) {
        unsigned v = (t >= (unsigned)off) ? ss[t - off] : 0u;
        __syncthreads();
        ss[t] += v;
        __syncthreads();
    }
    unsigned R = (mode == 0) ? (R_IDX - g_below[tn]) : g_rankin[tn];
    unsigned inc = ss[t];
    unsigned exc = inc - s;
    if (R >= exc && R < inc) {
        unsigned c = exc;
        for (int j = 0; j < 64; j++) {
            unsigned hh = h[t * 64 + j];
            if (R < c + hh) {
                if (mode == 0) {
                    g_bucket[tn] = t * 64 + j;
                    g_rankin[tn] = R - c;
                } else {
                    unsigned bits = (g_bucket[tn] << 16) | (t * 64 + j);
                    g_t[tn] = __uint_as_float(bits);
                }
                break;
            }
            c += hh;
        }
    }
}

// ---------------- level-2 histogram ----------------
__global__ void k_hist2(const float* __restrict__ x1, const float* __restrict__ x2) {
    unsigned bk0 = g_bucket[0], bk1 = g_bucket[1];
    for (int i = blockIdx.x * blockDim.x + threadIdx.x; i < N_ELEM;
         i += gridDim.x * blockDim.x) {
        unsigned b1 = __float_as_uint(x1[i]) & 0x7FFFFFFFu;
        if ((b1 >> 16) == bk0) atomicAdd(&g_hist2a[b1 & 0xFFFFu], 1u);
        unsigned b2 = __float_as_uint(x2[i]) & 0x7FFFFFFFu;
        if ((b2 >> 16) == bk1) atomicAdd(&g_hist2a[65536 + (b2 & 0xFFFFu)], 1u);
    }
}

// ---------------- HMMA GEMM ----------------
#define GA_AH 0
#define GA_AL 16384
#define GA_BH 32768
#define GA_BL 49152
#define GEMM_SMEM 65536

__global__ __launch_bounds__(256, 2)
void k_gemm_mma(const float* __restrict__ x1, const float* __restrict__ x2,
                float* __restrict__ out) {
    extern __shared__ char smem[];
    uint32_t sb = s2u(smem);
    int t = threadIdx.x, wid = t >> 5, lane = t & 31;
    int bh = blockIdx.z;
    int i0 = blockIdx.y * 128, j0 = blockIdx.x * 128;
    const float* A  = x1 + (size_t)bh * SLICE;
    const float* Bp = x2 + (size_t)bh * SLICE;

    for (int idx = t; idx < 2048; idx += 256) {
        int row = idx >> 4, k4 = (idx & 15) * 4;
        float4 v = *(const float4*)&A[(size_t)(i0 + row) * 64 + k4];
        __nv_bfloat16 h0 = __float2bfloat16(v.x), h1 = __float2bfloat16(v.y);
        __nv_bfloat16 h2 = __float2bfloat16(v.z), h3 = __float2bfloat16(v.w);
        __nv_bfloat16 l0 = __float2bfloat16(v.x - __bfloat162float(h0));
        __nv_bfloat16 l1 = __float2bfloat16(v.y - __bfloat162float(h1));
        __nv_bfloat16 l2 = __float2bfloat16(v.z - __bfloat162float(h2));
        __nv_bfloat16 l3 = __float2bfloat16(v.w - __bfloat162float(h3));
        uint2 uh, ul;
        uh.x = (unsigned)__bfloat16_as_ushort(h0) | ((unsigned)__bfloat16_as_ushort(h1) << 16);
        uh.y = (unsigned)__bfloat16_as_ushort(h2) | ((unsigned)__bfloat16_as_ushort(h3) << 16);
        ul.x = (unsigned)__bfloat16_as_ushort(l0) | ((unsigned)__bfloat16_as_ushort(l1) << 16);
        ul.y = (unsigned)__bfloat16_as_ushort(l2) | ((unsigned)__bfloat16_as_ushort(l3) << 16);
        uint32_t off = SWZ((unsigned)(row * 128 + k4 * 2));
        *(uint2*)(smem + GA_AH + off) = uh;
        *(uint2*)(smem + GA_AL + off) = ul;
    }
    {
        int n = (t & 31) * 4;
        int nblk = n >> 3;
        int nin  = n & 7;
        for (int k = t >> 5; k < 64; k += 8) {
            float4 v = *(const float4*)&Bp[(size_t)k * 2048 + j0 + n];
            __nv_bfloat16 h0 = __float2bfloat16(v.x), h1 = __float2bfloat16(v.y);
            __nv_bfloat16 h2 = __float2bfloat16(v.z), h3 = __float2bfloat16(v.w);
            __nv_bfloat16 l0 = __float2bfloat16(v.x - __bfloat162float(h0));
            __nv_bfloat16 l1 = __float2bfloat16(v.y - __bfloat162float(h1));
            __nv_bfloat16 l2 = __float2bfloat16(v.z - __bfloat162float(h2));
            __nv_bfloat16 l3 = __float2bfloat16(v.w - __bfloat162float(h3));
            uint2 uh, ul;
            uh.x = (unsigned)__bfloat16_as_ushort(h0) | ((unsigned)__bfloat16_as_ushort(h1) << 16);
            uh.y = (unsigned)__bfloat16_as_ushort(h2) | ((unsigned)__bfloat16_as_ushort(h3) << 16);
            ul.x = (unsigned)__bfloat16_as_ushort(l0) | ((unsigned)__bfloat16_as_ushort(l1) << 16);
            ul.y = (unsigned)__bfloat16_as_ushort(l2) | ((unsigned)__bfloat16_as_ushort(l3) << 16);
            int kk = k ^ (nblk & 7);
            uint32_t off = (unsigned)(nblk * 1024 + kk * 16 + nin * 2);
            *(uint2*)(smem + GA_BH + off) = uh;
            *(uint2*)(smem + GA_BL + off) = ul;
        }
    }
    __syncthreads();

    int wm = wid & 3, wn = wid >> 2;
    float acc[2][8][4];
    #pragma unroll
    for (int mt = 0; mt < 2; mt++)
        #pragma unroll
        for (int nt = 0; nt < 8; nt++)
            #pragma unroll
            for (int r = 0; r < 4; r++) acc[mt][nt][r] = 0.f;

    #pragma unroll
    for (int ks = 0; ks < 4; ks++) {
        uint32_t ah[2][4], al[2][4];
        #pragma unroll
        for (int mt = 0; mt < 2; mt++) {
            int row = wm * 32 + mt * 16 + (lane & 15);
            uint32_t boff = SWZ((unsigned)(row * 128 + ks * 32 + (lane >> 4) * 16));
            ldmat4(ah[mt][0], ah[mt][1], ah[mt][2], ah[mt][3], sb + GA_AH + boff);
            ldmat4(al[mt][0], al[mt][1], al[mt][2], al[mt][3], sb + GA_AL + boff);
        }
        #pragma unroll
        for (int p = 0; p < 4; p++) {
            int nblk = wn * 8 + p * 2 + (lane >> 4);
            int kidx = ks * 16 + (lane & 15);
            uint32_t boff = (unsigned)(nblk * 1024 + (kidx ^ (nblk & 7)) * 16);
            uint32_t bhr[4], blr[4];
            ldmat4t(bhr[0], bhr[1], bhr[2], bhr[3], sb + GA_BH + boff);
            ldmat4t(blr[0], blr[1], blr[2], blr[3], sb + GA_BL + boff);
            #pragma unroll
            for (int mt = 0; mt < 2; mt++) {
                #pragma unroll
                for (int h = 0; h < 2; h++) {
                    float* d = acc[mt][p * 2 + h];
                    mma16816(d, ah[mt], bhr[h * 2], bhr[h * 2 + 1]);
                    mma16816(d, ah[mt], blr[h * 2], blr[h * 2 + 1]);
                    mma16816(d, al[mt], bhr[h * 2], bhr[h * 2 + 1]);
                }
            }
        }
    }

    float* C = out + (size_t)bh * 4194304u;
    int g = lane >> 2, tg = lane & 3;
    #pragma unroll
    for (int mt = 0; mt < 2; mt++) {
        int row = i0 + wm * 32 + mt * 16 + g;
        #pragma unroll
        for (int nt = 0; nt < 8; nt++) {
            int col = j0 + wn * 64 + nt * 8 + tg * 2;
            float2 v0 = { acc[mt][nt][0], acc[mt][nt][1] };
            float2 v1 = { acc[mt][nt][2], acc[mt][nt][3] };
            *(float2*)&C[(size_t)row * 2048 + col] = v0;
            *(float2*)&C[(size_t)(row + 8) * 2048 + col] = v1;
        }
    }
}

// ---------------- LR1 = xm1 @ P1 ;  LR2T = P2 @ xm2T ----------------
__global__ void k_LR() {
    __shared__ float Ps[64 * 65];
    int tn = (blockIdx.x >= 512) ? 1 : 0;
    for (int i = threadIdx.x; i < 4096; i += 256)
        Ps[(i >> 6) * 65 + (i & 63)] = g_P[tn * 4096 + i];
    __syncthreads();
    int e = (blockIdx.x & 511) * 256 + threadIdx.x;
    if (tn == 0) {
        int s = e >> 6, d = e & 63;
        float sum = 0.f;
        #pragma unroll 8
        for (int k = 0; k < 64; k++)
            sum = fmaf(g_xm1[s * 64 + k], Ps[k * 65 + d], sum);
        g_LR1[e] = sum;
    } else {
        int d = e >> 11, si = e & 2047;
        float sum = 0.f;
        #pragma unroll 8
        for (int k = 0; k < 64; k++)
            sum = fmaf(Ps[d * 65 + k], g_xm2T[k * 2048 + si], sum);
        g_LR2T[e] = sum;
    }
}

// ---------------- max |sub| per tensor ----------------
__global__ void k_scale(const float* __restrict__ x1, const float* __restrict__ x2) {
    float t1 = g_t[0], t2 = g_t[1];
    unsigned m1 = 0, m2 = 0;
    for (int i = blockIdx.x * blockDim.x + threadIdx.x; i < N_ELEM;
         i += gridDim.x * blockDim.x) {
        int sl = i & (SLICE - 1);
        float v1 = x1[i];
        float f1 = ((fabsf(v1) > t1) ? 0.f : v1) - g_LR1[sl];
        m1 = max(m1, __float_as_uint(fabsf(f1)));
        float v2 = x2[i];
        float f2 = ((fabsf(v2) > t2) ? 0.f : v2) - g_LR2T[sl];
        m2 = max(m2, __float_as_uint(fabsf(f2)));
    }
    #pragma unroll
    for (int off = 16; off > 0; off >>= 1) {
        m1 = max(m1, __shfl_down_sync(0xFFFFFFFFu, m1, off));
        m2 = max(m2, __shfl_down_sync(0xFFFFFFFFu, m2, off));
    }
    if ((threadIdx.x & 31) == 0) {
        atomicMax(&g_maxbits[0], m1);
        atomicMax(&g_maxbits[1], m2);
    }
}

// ---------------- compress + decompress -> x1_hat, x2_hat ----------------
__global__ void k_hat(const float* __restrict__ x1, const float* __restrict__ x2,
                      float* __restrict__ out) {
    float t1 = g_t[0], t2 = g_t[1];
    float s1 = __fdiv_rn(__uint_as_float(g_maxbits[0]), 127.0f);
    float s2 = __fdiv_rn(__uint_as_float(g_maxbits[1]), 127.0f);
    for (int i = blockIdx.x * blockDim.x + threadIdx.x; i < N_ELEM;
         i += gridDim.x * blockDim.x) {
        int sl = i & (SLICE - 1);
        {
            float v = x1[i];
            float lr = g_LR1[sl];
            float o = (fabsf(v) > t1) ? v : 0.f;
            float sub = v - o - lr;
            float q = rintf(__fdiv_rn(sub, s1));
            q = fminf(fmaxf(q, -127.f), 127.f);
            out[OUT_HAT1 + i] = o + q * s1 + lr;
        }
        {
            float v = x2[i];
            float lr = g_LR2T[sl];
            float o = (fabsf(v) > t2) ? v : 0.f;
            float sub = v - o - lr;
            float q = rintf(__fdiv_rn(sub, s2));
            q = fminf(fmaxf(q, -127.f), 127.f);
            out[OUT_HAT2 + i] = o + q * s2 + lr;
        }
    }
}

// ---------------- launcher ----------------
extern "C" void kernel_launch(void* const* d_in, const int* in_sizes, int n_in,
                              void* d_out, int out_size) {
    const float* x1 = (const float*)d_in[0];
    const float* x2 = (const float*)d_in[1];
    float* out = (float*)d_out;

    static cudaStream_t s1 = 0, s2 = 0;
    static cudaEvent_t  e0 = 0, e1 = 0, e2 = 0, e3 = 0;
    if (s1 == 0) {
        int lo, hi;
        cudaDeviceGetStreamPriorityRange(&lo, &hi);
        cudaStreamCreateWithPriority(&s1, cudaStreamNonBlocking, lo);  // GEMM: low prio
        cudaStreamCreateWithPriority(&s2, cudaStreamNonBlocking, hi);  // stats: high prio
        cudaEventCreateWithFlags(&e0, cudaEventDisableTiming);
        cudaEventCreateWithFlags(&e1, cudaEventDisableTiming);
        cudaEventCreateWithFlags(&e2, cudaEventDisableTiming);
        cudaEventCreateWithFlags(&e3, cudaEventDisableTiming);
        cudaFuncSetAttribute(k_gemm_mma, cudaFuncAttributeMaxDynamicSharedMemorySize, GEMM_SMEM);
        cudaFuncSetAttribute(k_jacobi, cudaFuncAttributeMaxDynamicSharedMemorySize, JAC_BLOCK_SMEM);
    }

    cudaEventRecord(e0, 0);   // root marker for the GEMM

    // main stream: zero + means/hist1
    k_zero<<<512, 256>>>();
    k_mean_hist<<<512, 256>>>(x1, x2);

    // fork s2 (high prio): B -> jacobi -> LR (needs only the means)
    cudaEventRecord(e2, 0);
    cudaStreamWaitEvent(s2, e2, 0);
    k_B<<<32, 256, 0, s2>>>();
    k_jacobi<<<2, 1024, JAC_BLOCK_SMEM, s2>>>();
    k_LR<<<1024, 256, 0, s2>>>();
    cudaEventRecord(e3, s2);

    // main stream: quantile selection chain (overlaps jacobi)
    k_sel<<<2, 1024>>>(0);
    k_hist2<<<2048, 256>>>(x1, x2);
    k_sel<<<2, 1024>>>(1);

    // join stats chain, then scale + hat
    cudaStreamWaitEvent(0, e3, 0);
    k_scale<<<2048, 256>>>(x1, x2);
    k_hat<<<2048, 256>>>(x1, x2, out);

    // GEMM recorded LAST among roots (low prio stream, depends only on e0)
    cudaStreamWaitEvent(s1, e0, 0);
    k_gemm_mma<<<dim3(16, 16, 32), 256, GEMM_SMEM, s1>>>(x1, x2, out);
    cudaEventRecord(e1, s1);
    cudaStreamWaitEvent(0, e1, 0);
}

// round 14
// speedup vs baseline: 1.1320x; 1.1320x over previous
#include <cuda_runtime.h>
#include <cuda_bf16.h>
#include <math.h>
#include <stdint.h>

#define N_ELEM 4194304   // elements per tensor (2*16*2048*64)
#define SLICE  131072    // one batch-head slice
#define NBH    32
#define R_IDX  4152360u  // 0-based order-statistic index of the 0.99 quantile
#define OUT_HAT1  134217728u
#define OUT_HAT2  138412032u

// ---------------- device scratch ----------------
__device__ float    g_xm1[SLICE];
__device__ float    g_xm2T[SLICE];
__device__ unsigned g_hist1a[2 * 65536];
__device__ unsigned g_hist2a[2 * 65536];
__device__ unsigned g_below[2];
__device__ unsigned g_bucket[2];
__device__ unsigned g_rankin[2];
__device__ float    g_t[2];
__device__ unsigned g_maxbits[2];
__device__ float    g_Bpart[32 * 4096];
__device__ float    g_P[2 * 4096];
__device__ float    g_LR1[SLICE];
__device__ float    g_LR2T[SLICE];

// ---------------- helpers ----------------
__device__ __forceinline__ uint32_t s2u(const void* p) {
    uint32_t a;
    asm("{ .reg .u64 t; cvta.to.shared.u64 t, %1; cvt.u32.u64 %0, t; }" : "=r"(a) : "l"(p));
    return a;
}
#define SWZ(o) ((o) ^ (((o) >> 3) & 0x70))

__device__ __forceinline__ void ldmat4(uint32_t& r0, uint32_t& r1, uint32_t& r2, uint32_t& r3,
                                       uint32_t addr) {
    asm volatile("ldmatrix.sync.aligned.m8n8.x4.shared.b16 {%0,%1,%2,%3}, [%4];"
                 : "=r"(r0), "=r"(r1), "=r"(r2), "=r"(r3) : "r"(addr));
}
__device__ __forceinline__ void ldmat4t(uint32_t& r0, uint32_t& r1, uint32_t& r2, uint32_t& r3,
                                        uint32_t addr) {
    asm volatile("ldmatrix.sync.aligned.m8n8.x4.trans.shared.b16 {%0,%1,%2,%3}, [%4];"
                 : "=r"(r0), "=r"(r1), "=r"(r2), "=r"(r3) : "r"(addr));
}
__device__ __forceinline__ void mma16816(float* d, const uint32_t* a, uint32_t b0, uint32_t b1) {
    asm volatile(
        "mma.sync.aligned.m16n8k16.row.col.f32.bf16.bf16.f32 "
        "{%0,%1,%2,%3}, {%4,%5,%6,%7}, {%8,%9}, {%0,%1,%2,%3};"
        : "+f"(d[0]), "+f"(d[1]), "+f"(d[2]), "+f"(d[3])
        : "r"(a[0]), "r"(a[1]), "r"(a[2]), "r"(a[3]), "r"(b0), "r"(b1));
}

// ---------------- 1: means only (fast, runs alone at t=0) ----------------
__global__ __launch_bounds__(256)
void k_mean(const float* __restrict__ x1, const float* __restrict__ x2) {
    int i4 = blockIdx.x * blockDim.x + threadIdx.x;   // 0..32767 (SLICE/4)
    int base = i4 * 4;
    float4 s1 = make_float4(0.f, 0.f, 0.f, 0.f);
    float4 s2 = make_float4(0.f, 0.f, 0.f, 0.f);
    #pragma unroll 4
    for (int bh = 0; bh < NBH; bh++) {
        float4 v1 = *(const float4*)&x1[bh * SLICE + base];
        s1.x += v1.x; s1.y += v1.y; s1.z += v1.z; s1.w += v1.w;
        float4 v2 = *(const float4*)&x2[bh * SLICE + base];
        s2.x += v2.x; s2.y += v2.y; s2.z += v2.z; s2.w += v2.w;
    }
    s1.x *= 0.03125f; s1.y *= 0.03125f; s1.z *= 0.03125f; s1.w *= 0.03125f;
    s2.x *= 0.03125f; s2.y *= 0.03125f; s2.z *= 0.03125f; s2.w *= 0.03125f;
    *(float4*)&g_xm1[base]  = s1;
    *(float4*)&g_xm2T[base] = s2;
}

// ---------------- zero scratch ----------------
__global__ void k_zero() {
    int i = blockIdx.x * blockDim.x + threadIdx.x;
    if (i < 2 * 65536) { g_hist1a[i] = 0u; g_hist2a[i] = 0u; }
    if (i < 2) { g_below[i] = 0u; g_maxbits[i] = 0u; }
}

// ---------------- level-1 histogram (overlaps jacobi) ----------------
__global__ void k_hist1(const float* __restrict__ x1, const float* __restrict__ x2) {
    unsigned c1 = 0, c2 = 0;
    for (int i4 = blockIdx.x * blockDim.x + threadIdx.x; i4 < N_ELEM / 4;
         i4 += gridDim.x * blockDim.x) {
        float4 v1 = *(const float4*)&x1[i4 * 4];
        float4 v2 = *(const float4*)&x2[i4 * 4];
        const float* p1 = (const float*)&v1;
        const float* p2 = (const float*)&v2;
        #pragma unroll
        for (int j = 0; j < 4; j++) {
            unsigned b1 = __float_as_uint(p1[j]) & 0x7FFFFFFFu;
            if (b1 >= 0x40000000u) atomicAdd(&g_hist1a[b1 >> 16], 1u); else c1++;
            unsigned b2 = __float_as_uint(p2[j]) & 0x7FFFFFFFu;
            if (b2 >= 0x40000000u) atomicAdd(&g_hist1a[65536 + (b2 >> 16)], 1u); else c2++;
        }
    }
    #pragma unroll
    for (int off = 16; off > 0; off >>= 1) {
        c1 += __shfl_down_sync(0xFFFFFFFFu, c1, off);
        c2 += __shfl_down_sync(0xFFFFFFFFu, c2, off);
    }
    if ((threadIdx.x & 31) == 0) {
        atomicAdd(&g_below[0], c1);
        atomicAdd(&g_below[1], c2);
    }
}

// ---------------- B partials ----------------
__global__ __launch_bounds__(256, 1)
void k_B() {
    __shared__ float sm[128 * 72];
    int bid = blockIdx.x;
    int tn = bid >> 4, chunk = bid & 15;
    int t = threadIdx.x;
    int s0 = chunk * 128;

    if (tn == 0) {
        for (int idx = t; idx < 2048; idx += 256) {
            int row = idx >> 4, f4 = (idx & 15) * 4;
            float4 v = *(const float4*)&g_xm1[(s0 + row) * 64 + f4];
            *(float4*)&sm[row * 72 + f4] = v;
        }
    } else {
        for (int idx = t; idx < 2048; idx += 256) {
            int d = idx >> 5, sblk = (idx & 31) * 4;
            float4 v = *(const float4*)&g_xm2T[d * 2048 + s0 + sblk];
            sm[(sblk + 0) * 72 + d] = v.x;
            sm[(sblk + 1) * 72 + d] = v.y;
            sm[(sblk + 2) * 72 + d] = v.z;
            sm[(sblk + 3) * 72 + d] = v.w;
        }
    }
    __syncthreads();

    int d1 = t >> 2, d2b = (t & 3) * 16;
    float acc[16];
    #pragma unroll
    for (int j = 0; j < 16; j++) acc[j] = 0.f;
    for (int s = 0; s < 128; s++) {
        float a = sm[s * 72 + d1];
        const float4* bp = (const float4*)&sm[s * 72 + d2b];
        float4 b0 = bp[0], b1 = bp[1], b2 = bp[2], b3 = bp[3];
        acc[0]  = fmaf(a, b0.x, acc[0]);  acc[1]  = fmaf(a, b0.y, acc[1]);
        acc[2]  = fmaf(a, b0.z, acc[2]);  acc[3]  = fmaf(a, b0.w, acc[3]);
        acc[4]  = fmaf(a, b1.x, acc[4]);  acc[5]  = fmaf(a, b1.y, acc[5]);
        acc[6]  = fmaf(a, b1.z, acc[6]);  acc[7]  = fmaf(a, b1.w, acc[7]);
        acc[8]  = fmaf(a, b2.x, acc[8]);  acc[9]  = fmaf(a, b2.y, acc[9]);
        acc[10] = fmaf(a, b2.z, acc[10]); acc[11] = fmaf(a, b2.w, acc[11]);
        acc[12] = fmaf(a, b3.x, acc[12]); acc[13] = fmaf(a, b3.y, acc[13]);
        acc[14] = fmaf(a, b3.z, acc[14]); acc[15] = fmaf(a, b3.w, acc[15]);
    }
    float* dst = &g_Bpart[bid * 4096 + d1 * 64 + d2b];
    #pragma unroll
    for (int j = 0; j < 16; j++) dst[j] = acc[j];
}

// ---------------- Jacobi — two-phase (R10), 1024 threads, SM-exclusive ------
#define JAC_BLOCK_SMEM (150 * 1024)

__global__ __launch_bounds__(1024, 1)
void k_jacobi() {
    extern __shared__ char jac_pad[];   // occupancy blocker, untouched
    __shared__ float A[64 * 65];
    __shared__ float V[64 * 65];
    __shared__ int    pq[32];
    __shared__ float2 cs[32];
    __shared__ int   isTop[64], topIdx[16];
    int tn = blockIdx.x;
    int t = threadIdx.x;
    (void)jac_pad;

    #pragma unroll
    for (int k2 = 0; k2 < 4; k2++) {
        int idx = t + k2 * 1024;
        int r = idx >> 6, c = idx & 63;
        float a = 0.f;
        #pragma unroll 4
        for (int p = 0; p < 16; p++) a += g_Bpart[(tn * 16 + p) * 4096 + idx];
        A[r * 65 + c] = a;
        V[r * 65 + c] = (r == c) ? 1.f : 0.f;
    }
    __syncthreads();

    for (int rnd = 0; rnd < 6 * 63; rnd++) {
        int r = rnd % 63;
        if (t < 32) {
            int p, q;
            if (t == 0) { p = 0; q = 1 + r; }
            else {
                int a1 = r + t;      if (a1 >= 63) a1 -= 63;
                int a2 = r + 63 - t; if (a2 >= 63) a2 -= 63;
                p = 1 + a1; q = 1 + a2;
            }
            if (p > q) { int tmp = p; p = q; q = tmp; }
            float app = A[p * 65 + p], aqq = A[q * 65 + q], apq = A[p * 65 + q];
            float c = 1.f, s = 0.f;
            if (fabsf(apq) > 1e-20f) {
                float th = __fdividef(aqq - app, 2.0f * apq);
                float rr = __fsqrt_rn(fmaf(th, th, 1.f));
                float tt = __fdividef((th >= 0.f) ? 1.f : -1.f, fabsf(th) + rr);
                float ci = __frsqrt_rn(fmaf(tt, tt, 1.f));
                c = ci; s = tt * ci;
            }
            pq[t] = p | (q << 8);
            cs[t] = make_float2(c, s);
        }
        __syncthreads();
        // phase 1: column rotations of A and V (2 items/thread)
        #pragma unroll
        for (int k2 = 0; k2 < 2; k2++) {
            int idx = t + k2 * 1024;
            int pg = idx >> 6, row = idx & 63;
            int pk = pq[pg];
            int p = pk & 0xFF, q = pk >> 8;
            float2 csv = cs[pg];
            float c = csv.x, s = csv.y;
            float* Ar = &A[row * 65];
            float ap = Ar[p], aq = Ar[q];
            Ar[p] = c * ap - s * aq;
            Ar[q] = s * ap + c * aq;
            float* Vr = &V[row * 65];
            float vp = Vr[p], vq = Vr[q];
            Vr[p] = c * vp - s * vq;
            Vr[q] = s * vp + c * vq;
        }
        __syncthreads();
        // phase 2: row rotations of A (2 items/thread)
        #pragma unroll
        for (int k2 = 0; k2 < 2; k2++) {
            int idx = t + k2 * 1024;
            int pg = idx >> 6, col = idx & 63;
            int pk = pq[pg];
            int p = pk & 0xFF, q = pk >> 8;
            float2 csv = cs[pg];
            float c = csv.x, s = csv.y;
            float ap = A[p * 65 + col], aq = A[q * 65 + col];
            A[p * 65 + col] = c * ap - s * aq;
            A[q * 65 + col] = s * ap + c * aq;
        }
        __syncthreads();
    }

    if (t < 64) {
        float lam = A[t * 65 + t];
        int rank = 0;
        for (int j = 0; j < 64; j++) {
            float lj = A[j * 65 + j];
            if (lj > lam || (lj == lam && j < t)) rank++;
        }
        isTop[t] = (rank < 16) ? 1 : 0;
    }
    __syncthreads();
    if (t == 0) {
        int n = 0;
        for (int i = 0; i < 64; i++) if (isTop[i]) topIdx[n++] = i;
    }
    __syncthreads();
    #pragma unroll
    for (int k2 = 0; k2 < 4; k2++) {
        int idx = t + k2 * 1024;
        int r = idx >> 6, c = idx & 63;
        float sum = 0.f;
        #pragma unroll
        for (int k = 0; k < 16; k++) {
            int i = topIdx[k];
            sum = fmaf(V[r * 65 + i], V[c * 65 + i], sum);
        }
        g_P[tn * 4096 + idx] = sum;
    }
}

// ---------------- histogram select ----------------
__global__ void k_sel(int mode) {
    int tn = blockIdx.x;
    const unsigned* h = (mode == 0) ? &g_hist1a[tn * 65536] : &g_hist2a[tn * 65536];
    __shared__ unsigned ss[1024];
    unsigned t = threadIdx.x;
    unsigned s = 0;
    #pragma unroll 8
    for (int j = 0; j < 64; j++) s += h[t * 64 + j];
    ss[t] = s;
    __syncthreads();
    for (int off = 1; off < 1024; off <<= 1) {
        unsigned v = (t >= (unsigned)off) ? ss[t - off] : 0u;
        __syncthreads();
        ss[t] += v;
        __syncthreads();
    }
    unsigned R = (mode == 0) ? (R_IDX - g_below[tn]) : g_rankin[tn];
    unsigned inc = ss[t];
    unsigned exc = inc - s;
    if (R >= exc && R < inc) {
        unsigned c = exc;
        for (int j = 0; j < 64; j++) {
            unsigned hh = h[t * 64 + j];
            if (R < c + hh) {
                if (mode == 0) {
                    g_bucket[tn] = t * 64 + j;
                    g_rankin[tn] = R - c;
                } else {
                    unsigned bits = (g_bucket[tn] << 16) | (t * 64 + j);
                    g_t[tn] = __uint_as_float(bits);
                }
                break;
            }
            c += hh;
        }
    }
}

// ---------------- level-2 histogram ----------------
__global__ void k_hist2(const float* __restrict__ x1, const float* __restrict__ x2) {
    unsigned bk0 = g_bucket[0], bk1 = g_bucket[1];
    for (int i = blockIdx.x * blockDim.x + threadIdx.x; i < N_ELEM;
         i += gridDim.x * blockDim.x) {
        unsigned b1 = __float_as_uint(x1[i]) & 0x7FFFFFFFu;
        if ((b1 >> 16) == bk0) atomicAdd(&g_hist2a[b1 & 0xFFFFu], 1u);
        unsigned b2 = __float_as_uint(x2[i]) & 0x7FFFFFFFu;
        if ((b2 >> 16) == bk1) atomicAdd(&g_hist2a[65536 + (b2 & 0xFFFFu)], 1u);
    }
}

// ---------------- HMMA GEMM ----------------
#define GA_AH 0
#define GA_AL 16384
#define GA_BH 32768
#define GA_BL 49152
#define GEMM_SMEM 65536

__global__ __launch_bounds__(256, 2)
void k_gemm_mma(const float* __restrict__ x1, const float* __restrict__ x2,
                float* __restrict__ out) {
    extern __shared__ char smem[];
    uint32_t sb = s2u(smem);
    int t = threadIdx.x, wid = t >> 5, lane = t & 31;
    int bh = blockIdx.z;
    int i0 = blockIdx.y * 128, j0 = blockIdx.x * 128;
    const float* A  = x1 + (size_t)bh * SLICE;
    const float* Bp = x2 + (size_t)bh * SLICE;

    for (int idx = t; idx < 2048; idx += 256) {
        int row = idx >> 4, k4 = (idx & 15) * 4;
        float4 v = *(const float4*)&A[(size_t)(i0 + row) * 64 + k4];
        __nv_bfloat16 h0 = __float2bfloat16(v.x), h1 = __float2bfloat16(v.y);
        __nv_bfloat16 h2 = __float2bfloat16(v.z), h3 = __float2bfloat16(v.w);
        __nv_bfloat16 l0 = __float2bfloat16(v.x - __bfloat162float(h0));
        __nv_bfloat16 l1 = __float2bfloat16(v.y - __bfloat162float(h1));
        __nv_bfloat16 l2 = __float2bfloat16(v.z - __bfloat162float(h2));
        __nv_bfloat16 l3 = __float2bfloat16(v.w - __bfloat162float(h3));
        uint2 uh, ul;
        uh.x = (unsigned)__bfloat16_as_ushort(h0) | ((unsigned)__bfloat16_as_ushort(h1) << 16);
        uh.y = (unsigned)__bfloat16_as_ushort(h2) | ((unsigned)__bfloat16_as_ushort(h3) << 16);
        ul.x = (unsigned)__bfloat16_as_ushort(l0) | ((unsigned)__bfloat16_as_ushort(l1) << 16);
        ul.y = (unsigned)__bfloat16_as_ushort(l2) | ((unsigned)__bfloat16_as_ushort(l3) << 16);
        uint32_t off = SWZ((unsigned)(row * 128 + k4 * 2));
        *(uint2*)(smem + GA_AH + off) = uh;
        *(uint2*)(smem + GA_AL + off) = ul;
    }
    {
        int n = (t & 31) * 4;
        int nblk = n >> 3;
        int nin  = n & 7;
        for (int k = t >> 5; k < 64; k += 8) {
            float4 v = *(const float4*)&Bp[(size_t)k * 2048 + j0 + n];
            __nv_bfloat16 h0 = __float2bfloat16(v.x), h1 = __float2bfloat16(v.y);
            __nv_bfloat16 h2 = __float2bfloat16(v.z), h3 = __float2bfloat16(v.w);
            __nv_bfloat16 l0 = __float2bfloat16(v.x - __bfloat162float(h0));
            __nv_bfloat16 l1 = __float2bfloat16(v.y - __bfloat162float(h1));
            __nv_bfloat16 l2 = __float2bfloat16(v.z - __bfloat162float(h2));
            __nv_bfloat16 l3 = __float2bfloat16(v.w - __bfloat162float(h3));
            uint2 uh, ul;
            uh.x = (unsigned)__bfloat16_as_ushort(h0) | ((unsigned)__bfloat16_as_ushort(h1) << 16);
            uh.y = (unsigned)__bfloat16_as_ushort(h2) | ((unsigned)__bfloat16_as_ushort(h3) << 16);
            ul.x = (unsigned)__bfloat16_as_ushort(l0) | ((unsigned)__bfloat16_as_ushort(l1) << 16);
            ul.y = (unsigned)__bfloat16_as_ushort(l2) | ((unsigned)__bfloat16_as_ushort(l3) << 16);
            int kk = k ^ (nblk & 7);
            uint32_t off = (unsigned)(nblk * 1024 + kk * 16 + nin * 2);
            *(uint2*)(smem + GA_BH + off) = uh;
            *(uint2*)(smem + GA_BL + off) = ul;
        }
    }
    __syncthreads();

    int wm = wid & 3, wn = wid >> 2;
    float acc[2][8][4];
    #pragma unroll
    for (int mt = 0; mt < 2; mt++)
        #pragma unroll
        for (int nt = 0; nt < 8; nt++)
            #pragma unroll
            for (int r = 0; r < 4; r++) acc[mt][nt][r] = 0.f;

    #pragma unroll
    for (int ks = 0; ks < 4; ks++) {
        uint32_t ah[2][4], al[2][4];
        #pragma unroll
        for (int mt = 0; mt < 2; mt++) {
            int row = wm * 32 + mt * 16 + (lane & 15);
            uint32_t boff = SWZ((unsigned)(row * 128 + ks * 32 + (lane >> 4) * 16));
            ldmat4(ah[mt][0], ah[mt][1], ah[mt][2], ah[mt][3], sb + GA_AH + boff);
            ldmat4(al[mt][0], al[mt][1], al[mt][2], al[mt][3], sb + GA_AL + boff);
        }
        #pragma unroll
        for (int p = 0; p < 4; p++) {
            int nblk = wn * 8 + p * 2 + (lane >> 4);
            int kidx = ks * 16 + (lane & 15);
            uint32_t boff = (unsigned)(nblk * 1024 + (kidx ^ (nblk & 7)) * 16);
            uint32_t bhr[4], blr[4];
            ldmat4t(bhr[0], bhr[1], bhr[2], bhr[3], sb + GA_BH + boff);
            ldmat4t(blr[0], blr[1], blr[2], blr[3], sb + GA_BL + boff);
            #pragma unroll
            for (int mt = 0; mt < 2; mt++) {
                #pragma unroll
                for (int h = 0; h < 2; h++) {
                    float* d = acc[mt][p * 2 + h];
                    mma16816(d, ah[mt], bhr[h * 2], bhr[h * 2 + 1]);
                    mma16816(d, ah[mt], blr[h * 2], blr[h * 2 + 1]);
                    mma16816(d, al[mt], bhr[h * 2], bhr[h * 2 + 1]);
                }
            }
        }
    }

    float* C = out + (size_t)bh * 4194304u;
    int g = lane >> 2, tg = lane & 3;
    #pragma unroll
    for (int mt = 0; mt < 2; mt++) {
        int row = i0 + wm * 32 + mt * 16 + g;
        #pragma unroll
        for (int nt = 0; nt < 8; nt++) {
            int col = j0 + wn * 64 + nt * 8 + tg * 2;
            float2 v0 = { acc[mt][nt][0], acc[mt][nt][1] };
            float2 v1 = { acc[mt][nt][2], acc[mt][nt][3] };
            *(float2*)&C[(size_t)row * 2048 + col] = v0;
            *(float2*)&C[(size_t)(row + 8) * 2048 + col] = v1;
        }
    }
}

// ---------------- LR1 = xm1 @ P1 ;  LR2T = P2 @ xm2T ----------------
__global__ void k_LR() {
    __shared__ float Ps[64 * 65];
    int tn = (blockIdx.x >= 512) ? 1 : 0;
    for (int i = threadIdx.x; i < 4096; i += 256)
        Ps[(i >> 6) * 65 + (i & 63)] = g_P[tn * 4096 + i];
    __syncthreads();
    int e = (blockIdx.x & 511) * 256 + threadIdx.x;
    if (tn == 0) {
        int s = e >> 6, d = e & 63;
        float sum = 0.f;
        #pragma unroll 8
        for (int k = 0; k < 64; k++)
            sum = fmaf(g_xm1[s * 64 + k], Ps[k * 65 + d], sum);
        g_LR1[e] = sum;
    } else {
        int d = e >> 11, si = e & 2047;
        float sum = 0.f;
        #pragma unroll 8
        for (int k = 0; k < 64; k++)
            sum = fmaf(Ps[d * 65 + k], g_xm2T[k * 2048 + si], sum);
        g_LR2T[e] = sum;
    }
}

// ---------------- max |sub| per tensor ----------------
__global__ void k_scale(const float* __restrict__ x1, const float* __restrict__ x2) {
    float t1 = g_t[0], t2 = g_t[1];
    unsigned m1 = 0, m2 = 0;
    for (int i = blockIdx.x * blockDim.x + threadIdx.x; i < N_ELEM;
         i += gridDim.x * blockDim.x) {
        int sl = i & (SLICE - 1);
        float v1 = x1[i];
        float f1 = ((fabsf(v1) > t1) ? 0.f : v1) - g_LR1[sl];
        m1 = max(m1, __float_as_uint(fabsf(f1)));
        float v2 = x2[i];
        float f2 = ((fabsf(v2) > t2) ? 0.f : v2) - g_LR2T[sl];
        m2 = max(m2, __float_as_uint(fabsf(f2)));
    }
    #pragma unroll
    for (int off = 16; off > 0; off >>= 1) {
        m1 = max(m1, __shfl_down_sync(0xFFFFFFFFu, m1, off));
        m2 = max(m2, __shfl_down_sync(0xFFFFFFFFu, m2, off));
    }
    if ((threadIdx.x & 31) == 0) {
        atomicMax(&g_maxbits[0], m1);
        atomicMax(&g_maxbits[1], m2);
    }
}

// ---------------- compress + decompress -> x1_hat, x2_hat ----------------
__global__ void k_hat(const float* __restrict__ x1, const float* __restrict__ x2,
                      float* __restrict__ out) {
    float t1 = g_t[0], t2 = g_t[1];
    float s1 = __fdiv_rn(__uint_as_float(g_maxbits[0]), 127.0f);
    float s2 = __fdiv_rn(__uint_as_float(g_maxbits[1]), 127.0f);
    for (int i = blockIdx.x * blockDim.x + threadIdx.x; i < N_ELEM;
         i += gridDim.x * blockDim.x) {
        int sl = i & (SLICE - 1);
        {
            float v = x1[i];
            float lr = g_LR1[sl];
            float o = (fabsf(v) > t1) ? v : 0.f;
            float sub = v - o - lr;
            float q = rintf(__fdiv_rn(sub, s1));
            q = fminf(fmaxf(q, -127.f), 127.f);
            out[OUT_HAT1 + i] = o + q * s1 + lr;
        }
        {
            float v = x2[i];
            float lr = g_LR2T[sl];
            float o = (fabsf(v) > t2) ? v : 0.f;
            float sub = v - o - lr;
            float q = rintf(__fdiv_rn(sub, s2));
            q = fminf(fmaxf(q, -127.f), 127.f);
            out[OUT_HAT2 + i] = o + q * s2 + lr;
        }
    }
}

// ---------------- launcher: means first (clean chip), then fork everything ---
extern "C" void kernel_launch(void* const* d_in, const int* in_sizes, int n_in,
                              void* d_out, int out_size) {
    const float* x1 = (const float*)d_in[0];
    const float* x2 = (const float*)d_in[1];
    float* out = (float*)d_out;

    static cudaStream_t s1 = 0, s2 = 0;
    static cudaEvent_t  eM = 0, e1 = 0, e3 = 0;
    if (s1 == 0) {
        int lo, hi;
        cudaDeviceGetStreamPriorityRange(&lo, &hi);
        cudaStreamCreateWithPriority(&s1, cudaStreamNonBlocking, lo);  // GEMM: low prio
        cudaStreamCreateWithPriority(&s2, cudaStreamNonBlocking, hi);  // stats: high prio
        cudaEventCreateWithFlags(&eM, cudaEventDisableTiming);
        cudaEventCreateWithFlags(&e1, cudaEventDisableTiming);
        cudaEventCreateWithFlags(&e3, cudaEventDisableTiming);
        cudaFuncSetAttribute(k_gemm_mma, cudaFuncAttributeMaxDynamicSharedMemorySize, GEMM_SMEM);
        cudaFuncSetAttribute(k_jacobi, cudaFuncAttributeMaxDynamicSharedMemorySize, JAC_BLOCK_SMEM);
    }

    // stage 1: means alone on an empty chip (~10 us)
    k_mean<<<128, 256>>>(x1, x2);
    cudaEventRecord(eM, 0);

    // fork s2 (high prio): B -> jacobi -> LR  (the long serial chain)
    cudaStreamWaitEvent(s2, eM, 0);
    k_B<<<32, 256, 0, s2>>>();
    k_jacobi<<<2, 1024, JAC_BLOCK_SMEM, s2>>>();
    k_LR<<<1024, 256, 0, s2>>>();
    cudaEventRecord(e3, s2);

    // fork s1 (low prio): the GEMM — starts right after means
    cudaStreamWaitEvent(s1, eM, 0);
    k_gemm_mma<<<dim3(16, 16, 32), 256, GEMM_SMEM, s1>>>(x1, x2, out);
    cudaEventRecord(e1, s1);

    // main stream: quantile chain (overlaps jacobi + GEMM)
    k_zero<<<512, 256>>>();
    k_hist1<<<1024, 256>>>(x1, x2);
    k_sel<<<2, 1024>>>(0);
    k_hist2<<<2048, 256>>>(x1, x2);
    k_sel<<<2, 1024>>>(1);

    // join stats chain, then scale + hat
    cudaStreamWaitEvent(0, e3, 0);
    k_scale<<<2048, 256>>>(x1, x2);
    k_hat<<<2048, 256>>>(x1, x2, out);

    // join GEMM
    cudaStreamWaitEvent(0, e1, 0);
}

// round 15
// speedup vs baseline: 1.2029x; 1.0627x over previous
#include <cuda_runtime.h>
#include <cuda_bf16.h>
#include <math.h>
#include <stdint.h>

#define N_ELEM 4194304   // elements per tensor (2*16*2048*64)
#define SLICE  131072    // one batch-head slice
#define NBH    32
#define R_IDX  4152360u  // 0-based order-statistic index of the 0.99 quantile
#define OUT_HAT1  134217728u
#define OUT_HAT2  138412032u

// ---------------- device scratch ----------------
__device__ float    g_xm1[SLICE];
__device__ float    g_xm2T[SLICE];
__device__ unsigned g_hist1a[2 * 65536];
__device__ unsigned g_hist2a[2 * 65536];
__device__ unsigned g_below[2];
__device__ unsigned g_bucket[2];
__device__ unsigned g_rankin[2];
__device__ float    g_t[2];
__device__ unsigned g_maxbits[2];
__device__ float    g_Bpart[32 * 4096];
__device__ float    g_P[2 * 4096];
__device__ float    g_LR1[SLICE];
__device__ float    g_LR2T[SLICE];

// ---------------- helpers ----------------
__device__ __forceinline__ uint32_t s2u(const void* p) {
    uint32_t a;
    asm("{ .reg .u64 t; cvta.to.shared.u64 t, %1; cvt.u32.u64 %0, t; }" : "=r"(a) : "l"(p));
    return a;
}
#define SWZ(o) ((o) ^ (((o) >> 3) & 0x70))

__device__ __forceinline__ void ldmat4(uint32_t& r0, uint32_t& r1, uint32_t& r2, uint32_t& r3,
                                       uint32_t addr) {
    asm volatile("ldmatrix.sync.aligned.m8n8.x4.shared.b16 {%0,%1,%2,%3}, [%4];"
                 : "=r"(r0), "=r"(r1), "=r"(r2), "=r"(r3) : "r"(addr));
}
__device__ __forceinline__ void ldmat4t(uint32_t& r0, uint32_t& r1, uint32_t& r2, uint32_t& r3,
                                        uint32_t addr) {
    asm volatile("ldmatrix.sync.aligned.m8n8.x4.trans.shared.b16 {%0,%1,%2,%3}, [%4];"
                 : "=r"(r0), "=r"(r1), "=r"(r2), "=r"(r3) : "r"(addr));
}
__device__ __forceinline__ void mma16816(float* d, const uint32_t* a, uint32_t b0, uint32_t b1) {
    asm volatile(
        "mma.sync.aligned.m16n8k16.row.col.f32.bf16.bf16.f32 "
        "{%0,%1,%2,%3}, {%4,%5,%6,%7}, {%8,%9}, {%0,%1,%2,%3};"
        : "+f"(d[0]), "+f"(d[1]), "+f"(d[2]), "+f"(d[3])
        : "r"(a[0]), "r"(a[1]), "r"(a[2]), "r"(a[3]), "r"(b0), "r"(b1));
}
__device__ __forceinline__ void stcs2(float* p, float2 v) {
    asm volatile("st.global.cs.v2.f32 [%0], {%1, %2};" :: "l"(p), "f"(v.x), "f"(v.y) : "memory");
}
__device__ __forceinline__ void stcs1(float* p, float v) {
    asm volatile("st.global.cs.f32 [%0], %1;" :: "l"(p), "f"(v) : "memory");
}

// ---------------- 1: means only (fast, runs alone at t=0) ----------------
__global__ __launch_bounds__(256)
void k_mean(const float* __restrict__ x1, const float* __restrict__ x2) {
    int i4 = blockIdx.x * blockDim.x + threadIdx.x;   // 0..32767 (SLICE/4)
    int base = i4 * 4;
    float4 s1 = make_float4(0.f, 0.f, 0.f, 0.f);
    float4 s2 = make_float4(0.f, 0.f, 0.f, 0.f);
    #pragma unroll 4
    for (int bh = 0; bh < NBH; bh++) {
        float4 v1 = *(const float4*)&x1[bh * SLICE + base];
        s1.x += v1.x; s1.y += v1.y; s1.z += v1.z; s1.w += v1.w;
        float4 v2 = *(const float4*)&x2[bh * SLICE + base];
        s2.x += v2.x; s2.y += v2.y; s2.z += v2.z; s2.w += v2.w;
    }
    s1.x *= 0.03125f; s1.y *= 0.03125f; s1.z *= 0.03125f; s1.w *= 0.03125f;
    s2.x *= 0.03125f; s2.y *= 0.03125f; s2.z *= 0.03125f; s2.w *= 0.03125f;
    *(float4*)&g_xm1[base]  = s1;
    *(float4*)&g_xm2T[base] = s2;
}

// ---------------- zero scratch ----------------
__global__ void k_zero() {
    int i = blockIdx.x * blockDim.x + threadIdx.x;
    if (i < 2 * 65536) { g_hist1a[i] = 0u; g_hist2a[i] = 0u; }
    if (i < 2) { g_below[i] = 0u; g_maxbits[i] = 0u; }
}

// ---------------- level-1 histogram (overlaps jacobi) ----------------
__global__ void k_hist1(const float* __restrict__ x1, const float* __restrict__ x2) {
    unsigned c1 = 0, c2 = 0;
    for (int i4 = blockIdx.x * blockDim.x + threadIdx.x; i4 < N_ELEM / 4;
         i4 += gridDim.x * blockDim.x) {
        float4 v1 = *(const float4*)&x1[i4 * 4];
        float4 v2 = *(const float4*)&x2[i4 * 4];
        const float* p1 = (const float*)&v1;
        const float* p2 = (const float*)&v2;
        #pragma unroll
        for (int j = 0; j < 4; j++) {
            unsigned b1 = __float_as_uint(p1[j]) & 0x7FFFFFFFu;
            if (b1 >= 0x40000000u) atomicAdd(&g_hist1a[b1 >> 16], 1u); else c1++;
            unsigned b2 = __float_as_uint(p2[j]) & 0x7FFFFFFFu;
            if (b2 >= 0x40000000u) atomicAdd(&g_hist1a[65536 + (b2 >> 16)], 1u); else c2++;
        }
    }
    #pragma unroll
    for (int off = 16; off > 0; off >>= 1) {
        c1 += __shfl_down_sync(0xFFFFFFFFu, c1, off);
        c2 += __shfl_down_sync(0xFFFFFFFFu, c2, off);
    }
    if ((threadIdx.x & 31) == 0) {
        atomicAdd(&g_below[0], c1);
        atomicAdd(&g_below[1], c2);
    }
}

// ---------------- B partials ----------------
__global__ __launch_bounds__(256, 1)
void k_B() {
    __shared__ float sm[128 * 72];
    int bid = blockIdx.x;
    int tn = bid >> 4, chunk = bid & 15;
    int t = threadIdx.x;
    int s0 = chunk * 128;

    if (tn == 0) {
        for (int idx = t; idx < 2048; idx += 256) {
            int row = idx >> 4, f4 = (idx & 15) * 4;
            float4 v = *(const float4*)&g_xm1[(s0 + row) * 64 + f4];
            *(float4*)&sm[row * 72 + f4] = v;
        }
    } else {
        for (int idx = t; idx < 2048; idx += 256) {
            int d = idx >> 5, sblk = (idx & 31) * 4;
            float4 v = *(const float4*)&g_xm2T[d * 2048 + s0 + sblk];
            sm[(sblk + 0) * 72 + d] = v.x;
            sm[(sblk + 1) * 72 + d] = v.y;
            sm[(sblk + 2) * 72 + d] = v.z;
            sm[(sblk + 3) * 72 + d] = v.w;
        }
    }
    __syncthreads();

    int d1 = t >> 2, d2b = (t & 3) * 16;
    float acc[16];
    #pragma unroll
    for (int j = 0; j < 16; j++) acc[j] = 0.f;
    for (int s = 0; s < 128; s++) {
        float a = sm[s * 72 + d1];
        const float4* bp = (const float4*)&sm[s * 72 + d2b];
        float4 b0 = bp[0], b1 = bp[1], b2 = bp[2], b3 = bp[3];
        acc[0]  = fmaf(a, b0.x, acc[0]);  acc[1]  = fmaf(a, b0.y, acc[1]);
        acc[2]  = fmaf(a, b0.z, acc[2]);  acc[3]  = fmaf(a, b0.w, acc[3]);
        acc[4]  = fmaf(a, b1.x, acc[4]);  acc[5]  = fmaf(a, b1.y, acc[5]);
        acc[6]  = fmaf(a, b1.z, acc[6]);  acc[7]  = fmaf(a, b1.w, acc[7]);
        acc[8]  = fmaf(a, b2.x, acc[8]);  acc[9]  = fmaf(a, b2.y, acc[9]);
        acc[10] = fmaf(a, b2.z, acc[10]); acc[11] = fmaf(a, b2.w, acc[11]);
        acc[12] = fmaf(a, b3.x, acc[12]); acc[13] = fmaf(a, b3.y, acc[13]);
        acc[14] = fmaf(a, b3.z, acc[14]); acc[15] = fmaf(a, b3.w, acc[15]);
    }
    float* dst = &g_Bpart[bid * 4096 + d1 * 64 + d2b];
    #pragma unroll
    for (int j = 0; j < 16; j++) dst[j] = acc[j];
}

// ---------------- Jacobi — two-phase, 1024 threads, SM-exclusive ------
#define JAC_BLOCK_SMEM (150 * 1024)

__global__ __launch_bounds__(1024, 1)
void k_jacobi() {
    extern __shared__ char jac_pad[];   // occupancy blocker, untouched
    __shared__ float A[64 * 65];
    __shared__ float V[64 * 65];
    __shared__ int    pq[32];
    __shared__ float2 cs[32];
    __shared__ int   isTop[64], topIdx[16];
    int tn = blockIdx.x;
    int t = threadIdx.x;
    (void)jac_pad;

    #pragma unroll
    for (int k2 = 0; k2 < 4; k2++) {
        int idx = t + k2 * 1024;
        int r = idx >> 6, c = idx & 63;
        float a = 0.f;
        #pragma unroll 4
        for (int p = 0; p < 16; p++) a += g_Bpart[(tn * 16 + p) * 4096 + idx];
        A[r * 65 + c] = a;
        V[r * 65 + c] = (r == c) ? 1.f : 0.f;
    }
    __syncthreads();

    for (int rnd = 0; rnd < 6 * 63; rnd++) {
        int r = rnd % 63;
        if (t < 32) {
            int p, q;
            if (t == 0) { p = 0; q = 1 + r; }
            else {
                int a1 = r + t;      if (a1 >= 63) a1 -= 63;
                int a2 = r + 63 - t; if (a2 >= 63) a2 -= 63;
                p = 1 + a1; q = 1 + a2;
            }
            if (p > q) { int tmp = p; p = q; q = tmp; }
            float app = A[p * 65 + p], aqq = A[q * 65 + q], apq = A[p * 65 + q];
            float c = 1.f, s = 0.f;
            if (fabsf(apq) > 1e-20f) {
                float th = __fdividef(aqq - app, 2.0f * apq);
                float rr = __fsqrt_rn(fmaf(th, th, 1.f));
                float tt = __fdividef((th >= 0.f) ? 1.f : -1.f, fabsf(th) + rr);
                float ci = __frsqrt_rn(fmaf(tt, tt, 1.f));
                c = ci; s = tt * ci;
            }
            pq[t] = p | (q << 8);
            cs[t] = make_float2(c, s);
        }
        __syncthreads();
        // phase 1: column rotations of A and V (2 items/thread)
        #pragma unroll
        for (int k2 = 0; k2 < 2; k2++) {
            int idx = t + k2 * 1024;
            int pg = idx >> 6, row = idx & 63;
            int pk = pq[pg];
            int p = pk & 0xFF, q = pk >> 8;
            float2 csv = cs[pg];
            float c = csv.x, s = csv.y;
            float* Ar = &A[row * 65];
            float ap = Ar[p], aq = Ar[q];
            Ar[p] = c * ap - s * aq;
            Ar[q] = s * ap + c * aq;
            float* Vr = &V[row * 65];
            float vp = Vr[p], vq = Vr[q];
            Vr[p] = c * vp - s * vq;
            Vr[q] = s * vp + c * vq;
        }
        __syncthreads();
        // phase 2: row rotations of A (2 items/thread)
        #pragma unroll
        for (int k2 = 0; k2 < 2; k2++) {
            int idx = t + k2 * 1024;
            int pg = idx >> 6, col = idx & 63;
            int pk = pq[pg];
            int p = pk & 0xFF, q = pk >> 8;
            float2 csv = cs[pg];
            float c = csv.x, s = csv.y;
            float ap = A[p * 65 + col], aq = A[q * 65 + col];
            A[p * 65 + col] = c * ap - s * aq;
            A[q * 65 + col] = s * ap + c * aq;
        }
        __syncthreads();
    }

    if (t < 64) {
        float lam = A[t * 65 + t];
        int rank = 0;
        for (int j = 0; j < 64; j++) {
            float lj = A[j * 65 + j];
            if (lj > lam || (lj == lam && j < t)) rank++;
        }
        isTop[t] = (rank < 16) ? 1 : 0;
    }
    __syncthreads();
    if (t == 0) {
        int n = 0;
        for (int i = 0; i < 64; i++) if (isTop[i]) topIdx[n++] = i;
    }
    __syncthreads();
    #pragma unroll
    for (int k2 = 0; k2 < 4; k2++) {
        int idx = t + k2 * 1024;
        int r = idx >> 6, c = idx & 63;
        float sum = 0.f;
        #pragma unroll
        for (int k = 0; k < 16; k++) {
            int i = topIdx[k];
            sum = fmaf(V[r * 65 + i], V[c * 65 + i], sum);
        }
        g_P[tn * 4096 + idx] = sum;
    }
}

// ---------------- histogram select ----------------
__global__ void k_sel(int mode) {
    int tn = blockIdx.x;
    const unsigned* h = (mode == 0) ? &g_hist1a[tn * 65536] : &g_hist2a[tn * 65536];
    __shared__ unsigned ss[1024];
    unsigned t = threadIdx.x;
    unsigned s = 0;
    #pragma unroll 8
    for (int j = 0; j < 64; j++) s += h[t * 64 + j];
    ss[t] = s;
    __syncthreads();
    for (int off = 1; off < 1024; off <<= 1) {
        unsigned v = (t >= (unsigned)off) ? ss[t - off] : 0u;
        __syncthreads();
        ss[t] += v;
        __syncthreads();
    }
    unsigned R = (mode == 0) ? (R_IDX - g_below[tn]) : g_rankin[tn];
    unsigned inc = ss[t];
    unsigned exc = inc - s;
    if (R >= exc && R < inc) {
        unsigned c = exc;
        for (int j = 0; j < 64; j++) {
            unsigned hh = h[t * 64 + j];
            if (R < c + hh) {
                if (mode == 0) {
                    g_bucket[tn] = t * 64 + j;
                    g_rankin[tn] = R - c;
                } else {
                    unsigned bits = (g_bucket[tn] << 16) | (t * 64 + j);
                    g_t[tn] = __uint_as_float(bits);
                }
                break;
            }
            c += hh;
        }
    }
}

// ---------------- level-2 histogram ----------------
__global__ void k_hist2(const float* __restrict__ x1, const float* __restrict__ x2) {
    unsigned bk0 = g_bucket[0], bk1 = g_bucket[1];
    for (int i = blockIdx.x * blockDim.x + threadIdx.x; i < N_ELEM;
         i += gridDim.x * blockDim.x) {
        unsigned b1 = __float_as_uint(x1[i]) & 0x7FFFFFFFu;
        if ((b1 >> 16) == bk0) atomicAdd(&g_hist2a[b1 & 0xFFFFu], 1u);
        unsigned b2 = __float_as_uint(x2[i]) & 0x7FFFFFFFu;
        if ((b2 >> 16) == bk1) atomicAdd(&g_hist2a[65536 + (b2 & 0xFFFFu)], 1u);
    }
}

// ---------------- HMMA GEMM (now 3 CTAs/SM, streaming C stores) ----------------
#define GA_AH 0
#define GA_AL 16384
#define GA_BH 32768
#define GA_BL 49152
#define GEMM_SMEM 65536

__global__ __launch_bounds__(256, 3)
void k_gemm_mma(const float* __restrict__ x1, const float* __restrict__ x2,
                float* __restrict__ out) {
    extern __shared__ char smem[];
    uint32_t sb = s2u(smem);
    int t = threadIdx.x, wid = t >> 5, lane = t & 31;
    int bh = blockIdx.z;
    int i0 = blockIdx.y * 128, j0 = blockIdx.x * 128;
    const float* A  = x1 + (size_t)bh * SLICE;
    const float* Bp = x2 + (size_t)bh * SLICE;

    for (int idx = t; idx < 2048; idx += 256) {
        int row = idx >> 4, k4 = (idx & 15) * 4;
        float4 v = *(const float4*)&A[(size_t)(i0 + row) * 64 + k4];
        __nv_bfloat16 h0 = __float2bfloat16(v.x), h1 = __float2bfloat16(v.y);
        __nv_bfloat16 h2 = __float2bfloat16(v.z), h3 = __float2bfloat16(v.w);
        __nv_bfloat16 l0 = __float2bfloat16(v.x - __bfloat162float(h0));
        __nv_bfloat16 l1 = __float2bfloat16(v.y - __bfloat162float(h1));
        __nv_bfloat16 l2 = __float2bfloat16(v.z - __bfloat162float(h2));
        __nv_bfloat16 l3 = __float2bfloat16(v.w - __bfloat162float(h3));
        uint2 uh, ul;
        uh.x = (unsigned)__bfloat16_as_ushort(h0) | ((unsigned)__bfloat16_as_ushort(h1) << 16);
        uh.y = (unsigned)__bfloat16_as_ushort(h2) | ((unsigned)__bfloat16_as_ushort(h3) << 16);
        ul.x = (unsigned)__bfloat16_as_ushort(l0) | ((unsigned)__bfloat16_as_ushort(l1) << 16);
        ul.y = (unsigned)__bfloat16_as_ushort(l2) | ((unsigned)__bfloat16_as_ushort(l3) << 16);
        uint32_t off = SWZ((unsigned)(row * 128 + k4 * 2));
        *(uint2*)(smem + GA_AH + off) = uh;
        *(uint2*)(smem + GA_AL + off) = ul;
    }
    {
        int n = (t & 31) * 4;
        int nblk = n >> 3;
        int nin  = n & 7;
        for (int k = t >> 5; k < 64; k += 8) {
            float4 v = *(const float4*)&Bp[(size_t)k * 2048 + j0 + n];
            __nv_bfloat16 h0 = __float2bfloat16(v.x), h1 = __float2bfloat16(v.y);
            __nv_bfloat16 h2 = __float2bfloat16(v.z), h3 = __float2bfloat16(v.w);
            __nv_bfloat16 l0 = __float2bfloat16(v.x - __bfloat162float(h0));
            __nv_bfloat16 l1 = __float2bfloat16(v.y - __bfloat162float(h1));
            __nv_bfloat16 l2 = __float2bfloat16(v.z - __bfloat162float(h2));
            __nv_bfloat16 l3 = __float2bfloat16(v.w - __bfloat162float(h3));
            uint2 uh, ul;
            uh.x = (unsigned)__bfloat16_as_ushort(h0) | ((unsigned)__bfloat16_as_ushort(h1) << 16);
            uh.y = (unsigned)__bfloat16_as_ushort(h2) | ((unsigned)__bfloat16_as_ushort(h3) << 16);
            ul.x = (unsigned)__bfloat16_as_ushort(l0) | ((unsigned)__bfloat16_as_ushort(l1) << 16);
            ul.y = (unsigned)__bfloat16_as_ushort(l2) | ((unsigned)__bfloat16_as_ushort(l3) << 16);
            int kk = k ^ (nblk & 7);
            uint32_t off = (unsigned)(nblk * 1024 + kk * 16 + nin * 2);
            *(uint2*)(smem + GA_BH + off) = uh;
            *(uint2*)(smem + GA_BL + off) = ul;
        }
    }
    __syncthreads();

    int wm = wid & 3, wn = wid >> 2;
    float acc[2][8][4];
    #pragma unroll
    for (int mt = 0; mt < 2; mt++)
        #pragma unroll
        for (int nt = 0; nt < 8; nt++)
            #pragma unroll
            for (int r = 0; r < 4; r++) acc[mt][nt][r] = 0.f;

    #pragma unroll
    for (int ks = 0; ks < 4; ks++) {
        uint32_t ah[2][4], al[2][4];
        #pragma unroll
        for (int mt = 0; mt < 2; mt++) {
            int row = wm * 32 + mt * 16 + (lane & 15);
            uint32_t boff = SWZ((unsigned)(row * 128 + ks * 32 + (lane >> 4) * 16));
            ldmat4(ah[mt][0], ah[mt][1], ah[mt][2], ah[mt][3], sb + GA_AH + boff);
            ldmat4(al[mt][0], al[mt][1], al[mt][2], al[mt][3], sb + GA_AL + boff);
        }
        #pragma unroll
        for (int p = 0; p < 4; p++) {
            int nblk = wn * 8 + p * 2 + (lane >> 4);
            int kidx = ks * 16 + (lane & 15);
            uint32_t boff = (unsigned)(nblk * 1024 + (kidx ^ (nblk & 7)) * 16);
            uint32_t bhr[4], blr[4];
            ldmat4t(bhr[0], bhr[1], bhr[2], bhr[3], sb + GA_BH + boff);
            ldmat4t(blr[0], blr[1], blr[2], blr[3], sb + GA_BL + boff);
            #pragma unroll
            for (int mt = 0; mt < 2; mt++) {
                #pragma unroll
                for (int h = 0; h < 2; h++) {
                    float* d = acc[mt][p * 2 + h];
                    mma16816(d, ah[mt], bhr[h * 2], bhr[h * 2 + 1]);
                    mma16816(d, ah[mt], blr[h * 2], blr[h * 2 + 1]);
                    mma16816(d, al[mt], bhr[h * 2], bhr[h * 2 + 1]);
                }
            }
        }
    }

    float* C = out + (size_t)bh * 4194304u;
    int g = lane >> 2, tg = lane & 3;
    #pragma unroll
    for (int mt = 0; mt < 2; mt++) {
        int row = i0 + wm * 32 + mt * 16 + g;
        #pragma unroll
        for (int nt = 0; nt < 8; nt++) {
            int col = j0 + wn * 64 + nt * 8 + tg * 2;
            float2 v0 = { acc[mt][nt][0], acc[mt][nt][1] };
            float2 v1 = { acc[mt][nt][2], acc[mt][nt][3] };
            stcs2(&C[(size_t)row * 2048 + col], v0);
            stcs2(&C[(size_t)(row + 8) * 2048 + col], v1);
        }
    }
}

// ---------------- LR1 = xm1 @ P1 ;  LR2T = P2 @ xm2T ----------------
__global__ void k_LR() {
    __shared__ float Ps[64 * 65];
    int tn = (blockIdx.x >= 512) ? 1 : 0;
    for (int i = threadIdx.x; i < 4096; i += 256)
        Ps[(i >> 6) * 65 + (i & 63)] = g_P[tn * 4096 + i];
    __syncthreads();
    int e = (blockIdx.x & 511) * 256 + threadIdx.x;
    if (tn == 0) {
        int s = e >> 6, d = e & 63;
        float sum = 0.f;
        #pragma unroll 8
        for (int k = 0; k < 64; k++)
            sum = fmaf(g_xm1[s * 64 + k], Ps[k * 65 + d], sum);
        g_LR1[e] = sum;
    } else {
        int d = e >> 11, si = e & 2047;
        float sum = 0.f;
        #pragma unroll 8
        for (int k = 0; k < 64; k++)
            sum = fmaf(Ps[d * 65 + k], g_xm2T[k * 2048 + si], sum);
        g_LR2T[e] = sum;
    }
}

// ---------------- max |sub| per tensor ----------------
__global__ void k_scale(const float* __restrict__ x1, const float* __restrict__ x2) {
    float t1 = g_t[0], t2 = g_t[1];
    unsigned m1 = 0, m2 = 0;
    for (int i = blockIdx.x * blockDim.x + threadIdx.x; i < N_ELEM;
         i += gridDim.x * blockDim.x) {
        int sl = i & (SLICE - 1);
        float v1 = x1[i];
        float f1 = ((fabsf(v1) > t1) ? 0.f : v1) - g_LR1[sl];
        m1 = max(m1, __float_as_uint(fabsf(f1)));
        float v2 = x2[i];
        float f2 = ((fabsf(v2) > t2) ? 0.f : v2) - g_LR2T[sl];
        m2 = max(m2, __float_as_uint(fabsf(f2)));
    }
    #pragma unroll
    for (int off = 16; off > 0; off >>= 1) {
        m1 = max(m1, __shfl_down_sync(0xFFFFFFFFu, m1, off));
        m2 = max(m2, __shfl_down_sync(0xFFFFFFFFu, m2, off));
    }
    if ((threadIdx.x & 31) == 0) {
        atomicMax(&g_maxbits[0], m1);
        atomicMax(&g_maxbits[1], m2);
    }
}

// ---------------- compress + decompress -> x1_hat, x2_hat ----------------
__global__ void k_hat(const float* __restrict__ x1, const float* __restrict__ x2,
                      float* __restrict__ out) {
    float t1 = g_t[0], t2 = g_t[1];
    float s1 = __fdiv_rn(__uint_as_float(g_maxbits[0]), 127.0f);
    float s2 = __fdiv_rn(__uint_as_float(g_maxbits[1]), 127.0f);
    for (int i = blockIdx.x * blockDim.x + threadIdx.x; i < N_ELEM;
         i += gridDim.x * blockDim.x) {
        int sl = i & (SLICE - 1);
        {
            float v = x1[i];
            float lr = g_LR1[sl];
            float o = (fabsf(v) > t1) ? v : 0.f;
            float sub = v - o - lr;
            float q = rintf(__fdiv_rn(sub, s1));
            q = fminf(fmaxf(q, -127.f), 127.f);
            stcs1(&out[OUT_HAT1 + i], o + q * s1 + lr);
        }
        {
            float v = x2[i];
            float lr = g_LR2T[sl];
            float o = (fabsf(v) > t2) ? v : 0.f;
            float sub = v - o - lr;
            float q = rintf(__fdiv_rn(sub, s2));
            q = fminf(fmaxf(q, -127.f), 127.f);
            stcs1(&out[OUT_HAT2 + i], o + q * s2 + lr);
        }
    }
}

// ---------------- launcher: means first (clean chip), then fork everything ---
extern "C" void kernel_launch(void* const* d_in, const int* in_sizes, int n_in,
                              void* d_out, int out_size) {
    const float* x1 = (const float*)d_in[0];
    const float* x2 = (const float*)d_in[1];
    float* out = (float*)d_out;

    static cudaStream_t s1 = 0, s2 = 0;
    static cudaEvent_t  eM = 0, e1 = 0, e3 = 0;
    if (s1 == 0) {
        int lo, hi;
        cudaDeviceGetStreamPriorityRange(&lo, &hi);
        cudaStreamCreateWithPriority(&s1, cudaStreamNonBlocking, lo);  // GEMM: low prio
        cudaStreamCreateWithPriority(&s2, cudaStreamNonBlocking, hi);  // stats: high prio
        cudaEventCreateWithFlags(&eM, cudaEventDisableTiming);
        cudaEventCreateWithFlags(&e1, cudaEventDisableTiming);
        cudaEventCreateWithFlags(&e3, cudaEventDisableTiming);
        cudaFuncSetAttribute(k_gemm_mma, cudaFuncAttributeMaxDynamicSharedMemorySize, GEMM_SMEM);
        cudaFuncSetAttribute(k_jacobi, cudaFuncAttributeMaxDynamicSharedMemorySize, JAC_BLOCK_SMEM);
    }

    // stage 1: means alone on an empty chip (~10 us)
    k_mean<<<128, 256>>>(x1, x2);
    cudaEventRecord(eM, 0);

    // fork s2 (high prio): B -> jacobi -> LR  (the long serial chain)
    cudaStreamWaitEvent(s2, eM, 0);
    k_B<<<32, 256, 0, s2>>>();
    k_jacobi<<<2, 1024, JAC_BLOCK_SMEM, s2>>>();
    k_LR<<<1024, 256, 0, s2>>>();
    cudaEventRecord(e3, s2);

    // fork s1 (low prio): the GEMM — starts right after means
    cudaStreamWaitEvent(s1, eM, 0);
    k_gemm_mma<<<dim3(16, 16, 32), 256, GEMM_SMEM, s1>>>(x1, x2, out);
    cudaEventRecord(e1, s1);

    // main stream: quantile chain (overlaps jacobi + GEMM)
    k_zero<<<512, 256>>>();
    k_hist1<<<1024, 256>>>(x1, x2);
    k_sel<<<2, 1024>>>(0);
    k_hist2<<<2048, 256>>>(x1, x2);
    k_sel<<<2, 1024>>>(1);

    // join stats chain, then scale + hat
    cudaStreamWaitEvent(0, e3, 0);
    k_scale<<<1184, 256>>>(x1, x2);
    k_hat<<<1184, 256>>>(x1, x2, out);

    // join GEMM
    cudaStreamWaitEvent(0, e1, 0);
}